// round 1
// baseline (speedup 1.0000x reference)
#include <cuda_runtime.h>

// Inputs (metadata order):
//  0: link_pos_seq   [1024,32,8,3]    f32
//  1: link_rot_seq   [1024,32,8,3,3]  f32
//  2: sphere_centers [8,8,3]          f32
//  3: sphere_radii   [8,8]            f32
//  4: sdf_grid       [256,256,256]    f32
//  5: weight         scalar           f32
// Output: [1024,32] f32

#define GRID_N 256
#define N_LINKS 8
#define N_SPH 8

__global__ __launch_bounds__(256, 8)
void voxel_collision_kernel(const float* __restrict__ pos,
                            const float* __restrict__ rot,
                            const float* __restrict__ cen,
                            const float* __restrict__ rad,
                            const float* __restrict__ sdf,
                            const float* __restrict__ wptr,
                            float* __restrict__ out) {
    __shared__ float s_cen[N_LINKS * N_SPH * 3];   // 192 floats
    __shared__ float s_rad[N_LINKS * N_SPH];       // 64 floats

    const int tid = threadIdx.x;
    if (tid < N_LINKS * N_SPH * 3) s_cen[tid] = cen[tid];
    if (tid < N_LINKS * N_SPH)     s_rad[tid] = rad[tid];
    __syncthreads();

    const int g = blockIdx.x * 256 + tid;          // 0 .. 262143 = bh*8 + l
    const int l = g & 7;

    // Load rotation (9 consecutive floats) and position (3 consecutive floats).
    const float* R = rot + (size_t)g * 9;
    const float r00 = __ldg(R + 0), r01 = __ldg(R + 1), r02 = __ldg(R + 2);
    const float r10 = __ldg(R + 3), r11 = __ldg(R + 4), r12 = __ldg(R + 5);
    const float r20 = __ldg(R + 6), r21 = __ldg(R + 7), r22 = __ldg(R + 8);
    const float* P = pos + (size_t)g * 3;
    const float px = __ldg(P + 0), py = __ldg(P + 1), pz = __ldg(P + 2);

    const float* lc = s_cen + l * (N_SPH * 3);
    const float* lr = s_rad + l * N_SPH;

    float m = -3.402823466e+38f;
    #pragma unroll
    for (int s = 0; s < N_SPH; s++) {
        const float cx = lc[s * 3 + 0];
        const float cy = lc[s * 3 + 1];
        const float cz = lc[s * 3 + 2];
        // world point = R @ c + p
        const float x = fmaf(r00, cx, fmaf(r01, cy, fmaf(r02, cz, px)));
        const float y = fmaf(r10, cx, fmaf(r11, cy, fmaf(r12, cz, py)));
        const float z = fmaf(r20, cx, fmaf(r21, cy, fmaf(r22, cz, pz)));
        // voxel index: floor((p - (-1.28)) / 0.01), clipped to [0,255].
        // IEEE division to exactly match XLA (fast-math recip could flip floor).
        int i0 = (int)floorf(__fdiv_rn(x + 1.28f, 0.01f));
        int i1 = (int)floorf(__fdiv_rn(y + 1.28f, 0.01f));
        int i2 = (int)floorf(__fdiv_rn(z + 1.28f, 0.01f));
        i0 = min(max(i0, 0), GRID_N - 1);
        i1 = min(max(i1, 0), GRID_N - 1);
        i2 = min(max(i2, 0), GRID_N - 1);
        const float v = __ldg(sdf + (((size_t)i0 << 16) | (i1 << 8) | i2));
        m = fmaxf(m, lr[s] - v);
    }

    // threshold / clamp / normalize: clip(m - 0.01, 0, 0.5) / 0.25
    float res = fminf(fmaxf(m - 0.01f, 0.0f), 0.5f) * 4.0f;

    // sum over the 8 links (adjacent lanes within the warp)
    res += __shfl_xor_sync(0xffffffffu, res, 1);
    res += __shfl_xor_sync(0xffffffffu, res, 2);
    res += __shfl_xor_sync(0xffffffffu, res, 4);

    if (l == 0) out[g >> 3] = __ldg(wptr) * res;
}

extern "C" void kernel_launch(void* const* d_in, const int* in_sizes, int n_in,
                              void* d_out, int out_size) {
    const float* pos = (const float*)d_in[0];
    const float* rot = (const float*)d_in[1];
    const float* cen = (const float*)d_in[2];
    const float* rad = (const float*)d_in[3];
    const float* sdf = (const float*)d_in[4];
    const float* w   = (const float*)d_in[5];
    float* out = (float*)d_out;

    // 1024*32*8 = 262144 threads, 256 per block
    voxel_collision_kernel<<<1024, 256>>>(pos, rot, cen, rad, sdf, w, out);
}